// round 5
// baseline (speedup 1.0000x reference)
#include <cuda_runtime.h>
#include <cuda_bf16.h>
#include <cstdint>
#include <cstddef>

#define BATCH 2048
#define T_STEPS 128
#define HID 512
#define NCMD 3
#define NOUT 5
#define G3 1536

typedef __nv_bfloat16 bf16;

#define MT 128
#define JT 32
#define NTILE 96
#define KC 32
#define KPAD 40
#define A_BYTES (MT * KPAD * 2)               // 10240
#define B_BYTES (NTILE * KPAD * 2)            // 7680
#define STAGE_BYTES (2 * A_BYTES + 2 * B_BYTES)  // 35840
#define SMEM_BYTES (2 * STAGE_BYTES)             // 71680
#define S_STRIDE 100
#define XS_OFF 51200
#define W1_OFF (51200 + 4096)

__device__ float g_h1f[BATCH * HID];
__device__ float g_h2f[BATCH * HID];
__device__ bf16 g_h1hi[2][BATCH * HID];
__device__ bf16 g_h1lo[2][BATCH * HID];
__device__ bf16 g_h2hi[2][BATCH * HID];
__device__ bf16 g_h2lo[2][BATCH * HID];
__device__ bf16 g_whh1hi[G3 * HID];
__device__ bf16 g_whh1lo[G3 * HID];
__device__ bf16 g_wih2hi[G3 * HID];
__device__ bf16 g_wih2lo[G3 * HID];
__device__ bf16 g_whh2hi[G3 * HID];
__device__ bf16 g_whh2lo[G3 * HID];
__device__ float g_gi[(size_t)BATCH * G3];
__device__ float g_y[BATCH * NOUT];

__device__ __forceinline__ void cp8(void* dst, const void* src) {
    unsigned s = (unsigned)__cvta_generic_to_shared(dst);
    asm volatile("cp.async.ca.shared.global [%0], [%1], 8;\n" ::"r"(s), "l"(src));
}

__device__ __forceinline__ void mma16816(float* c, const uint32_t* a, const uint32_t* b) {
    asm volatile(
        "mma.sync.aligned.m16n8k16.row.col.f32.bf16.bf16.f32 "
        "{%0,%1,%2,%3}, {%4,%5,%6,%7}, {%8,%9}, {%0,%1,%2,%3};\n"
        : "+f"(c[0]), "+f"(c[1]), "+f"(c[2]), "+f"(c[3])
        : "r"(a[0]), "r"(a[1]), "r"(a[2]), "r"(a[3]), "r"(b[0]), "r"(b[1]));
}

// load one K-chunk: A(128x32) hi/lo + B(96x32) hi/lo, 8B cp.async each.
// 3584 transfers / 256 threads = 14 per thread.
__device__ __forceinline__ void load_chunk(
    int c, char* stage, int tid, int mBase, int jBase,
    const bf16* __restrict__ Ahi, const bf16* __restrict__ Alo,
    const bf16* __restrict__ Whi, const bf16* __restrict__ Wlo) {
    const int k0 = c * KC;
#pragma unroll
    for (int it = 0; it < 14; ++it) {
        int i = tid + it * 256;
        const bf16* src;
        char* dst;
        if (i < 2048) {  // A
            const bf16* Ab = (i < 1024) ? Ahi : Alo;
            char* db = stage + ((i < 1024) ? 0 : A_BYTES);
            int rr = i & 1023;
            int r = rr >> 3, c8 = rr & 7;
            src = Ab + (size_t)(mBase + r) * HID + k0 + c8 * 4;
            dst = db + r * (KPAD * 2) + c8 * 8;
        } else {  // B
            int ii = i - 2048;
            const bf16* Wb = (ii < 768) ? Whi : Wlo;
            char* db = stage + 2 * A_BYTES + ((ii < 768) ? 0 : B_BYTES);
            int rr = (ii < 768) ? ii : (ii - 768);
            int r = rr >> 3, c8 = rr & 7;
            int wrow = (r >> 5) * HID + jBase + (r & 31);
            src = Wb + (size_t)wrow * HID + k0 + c8 * 4;
            dst = db + r * (KPAD * 2) + c8 * 8;
        }
        cp8(dst, src);
    }
}

// MODE 0: gi_out = A@W^T + bias_h          (layer-2 gi -> scratch)
// MODE 1: layer1 fused: gh1 GEMM + gi1(K=8 from x=[y,cmd]) + GRU update
// MODE 2: layer2 fused: gh2 GEMM + gi from scratch + GRU update
template <int MODE>
__global__ void __launch_bounds__(256) fused_step(
    const bf16* __restrict__ Ahi, const bf16* __restrict__ Alo,
    const bf16* __restrict__ Whi, const bf16* __restrict__ Wlo,
    const float* __restrict__ bias_h, const float* __restrict__ gi_scr,
    float* __restrict__ gi_out, float* __restrict__ hf,
    bf16* __restrict__ out_hi, bf16* __restrict__ out_lo,
    const float* __restrict__ ybuf, const float* __restrict__ cmd_t,
    const float* __restrict__ Wih1, const float* __restrict__ bih1) {
    extern __shared__ char smem[];
    const int tid = threadIdx.x;
    const int lane = tid & 31;
    const int wid = tid >> 5;
    const int warpM = wid & 3;
    const int warpN = wid >> 2;
    const int mBase = blockIdx.x * MT;
    const int jBase = blockIdx.y * JT;
    const int g = lane >> 2, q = lane & 3;

    float acc[2][6][4];
#pragma unroll
    for (int a = 0; a < 2; ++a)
#pragma unroll
        for (int b = 0; b < 6; ++b)
#pragma unroll
            for (int e = 0; e < 4; ++e) acc[a][b][e] = 0.f;

    load_chunk(0, smem, tid, mBase, jBase, Ahi, Alo, Whi, Wlo);
    asm volatile("cp.async.commit_group;\n");
    for (int c = 0; c < HID / KC; ++c) {
        char* cur = smem + (c & 1) * STAGE_BYTES;
        if (c + 1 < HID / KC) {
            load_chunk(c + 1, smem + ((c + 1) & 1) * STAGE_BYTES, tid, mBase, jBase,
                       Ahi, Alo, Whi, Wlo);
            asm volatile("cp.async.commit_group;\n");
            asm volatile("cp.async.wait_group 1;\n");
        } else {
            asm volatile("cp.async.wait_group 0;\n");
        }
        __syncthreads();

        const bf16* sAh = (const bf16*)(cur);
        const bf16* sAl = (const bf16*)(cur + A_BYTES);
        const bf16* sBh = (const bf16*)(cur + 2 * A_BYTES);
        const bf16* sBl = (const bf16*)(cur + 2 * A_BYTES + B_BYTES);
#pragma unroll
        for (int kb = 0; kb < KC; kb += 16) {
            uint32_t a_hi[2][4], a_lo[2][4], b_hi[6][2], b_lo[6][2];
#pragma unroll
            for (int mt = 0; mt < 2; ++mt) {
                int r0 = warpM * 32 + mt * 16;
                a_hi[mt][0] = *(const uint32_t*)(sAh + (r0 + g) * KPAD + kb + q * 2);
                a_hi[mt][1] = *(const uint32_t*)(sAh + (r0 + g + 8) * KPAD + kb + q * 2);
                a_hi[mt][2] = *(const uint32_t*)(sAh + (r0 + g) * KPAD + kb + q * 2 + 8);
                a_hi[mt][3] = *(const uint32_t*)(sAh + (r0 + g + 8) * KPAD + kb + q * 2 + 8);
            }
#pragma unroll
            for (int nt = 0; nt < 6; ++nt) {
                int n0 = warpN * 48 + nt * 8 + g;
                b_hi[nt][0] = *(const uint32_t*)(sBh + n0 * KPAD + kb + q * 2);
                b_hi[nt][1] = *(const uint32_t*)(sBh + n0 * KPAD + kb + q * 2 + 8);
            }
#pragma unroll
            for (int mt = 0; mt < 2; ++mt)
#pragma unroll
                for (int nt = 0; nt < 6; ++nt) mma16816(acc[mt][nt], a_hi[mt], b_hi[nt]);
#pragma unroll
            for (int nt = 0; nt < 6; ++nt) {
                int n0 = warpN * 48 + nt * 8 + g;
                b_lo[nt][0] = *(const uint32_t*)(sBl + n0 * KPAD + kb + q * 2);
                b_lo[nt][1] = *(const uint32_t*)(sBl + n0 * KPAD + kb + q * 2 + 8);
            }
#pragma unroll
            for (int mt = 0; mt < 2; ++mt)
#pragma unroll
                for (int nt = 0; nt < 6; ++nt) mma16816(acc[mt][nt], a_hi[mt], b_lo[nt]);
#pragma unroll
            for (int mt = 0; mt < 2; ++mt) {
                int r0 = warpM * 32 + mt * 16;
                a_lo[mt][0] = *(const uint32_t*)(sAl + (r0 + g) * KPAD + kb + q * 2);
                a_lo[mt][1] = *(const uint32_t*)(sAl + (r0 + g + 8) * KPAD + kb + q * 2);
                a_lo[mt][2] = *(const uint32_t*)(sAl + (r0 + g) * KPAD + kb + q * 2 + 8);
                a_lo[mt][3] = *(const uint32_t*)(sAl + (r0 + g + 8) * KPAD + kb + q * 2 + 8);
            }
#pragma unroll
            for (int mt = 0; mt < 2; ++mt)
#pragma unroll
                for (int nt = 0; nt < 6; ++nt) mma16816(acc[mt][nt], a_lo[mt], b_hi[nt]);
        }
        __syncthreads();
    }

    if (MODE == 0) {
#pragma unroll
        for (int mt = 0; mt < 2; ++mt)
#pragma unroll
            for (int nt = 0; nt < 6; ++nt) {
                int rA = mBase + warpM * 32 + mt * 16 + g;
                int cc = warpN * 48 + nt * 8 + q * 2;
                int n1 = (cc >> 5) * HID + jBase + (cc & 31);
                float b0v = bias_h[n1], b1v = bias_h[n1 + 1];
                float* d0 = gi_out + (size_t)rA * G3 + n1;
                d0[0] = acc[mt][nt][0] + b0v;
                d0[1] = acc[mt][nt][1] + b1v;
                float* d1 = gi_out + (size_t)(rA + 8) * G3 + n1;
                d1[0] = acc[mt][nt][2] + b0v;
                d1[1] = acc[mt][nt][3] + b1v;
            }
        return;
    }

    // stage gh tile to smem so threads can gather full gate triples
    float* S = (float*)smem;
#pragma unroll
    for (int mt = 0; mt < 2; ++mt)
#pragma unroll
        for (int nt = 0; nt < 6; ++nt) {
            int r0 = warpM * 32 + mt * 16 + g;
            int cc = warpN * 48 + nt * 8 + q * 2;
            S[r0 * S_STRIDE + cc] = acc[mt][nt][0];
            S[r0 * S_STRIDE + cc + 1] = acc[mt][nt][1];
            S[(r0 + 8) * S_STRIDE + cc] = acc[mt][nt][2];
            S[(r0 + 8) * S_STRIDE + cc + 1] = acc[mt][nt][3];
        }
    float* xs = (float*)(smem + XS_OFF);
    float* w1 = (float*)(smem + W1_OFF);
    if (MODE == 1) {
        for (int i = tid; i < MT * 8; i += 256) {
            int r = i >> 3, k = i & 7;
            xs[i] = (k < NOUT) ? ybuf[(mBase + r) * NOUT + k]
                               : cmd_t[(size_t)(mBase + r) * NCMD + (k - NOUT)];
        }
        for (int i = tid; i < NTILE * 8; i += 256) {
            int n = i >> 3, k = i & 7;
            int wr = (n >> 5) * HID + jBase + (n & 31);
            w1[i] = Wih1[wr * 8 + k];
        }
    }
    __syncthreads();

    for (int i = tid; i < MT * JT; i += 256) {
        int jj = i & 31, r = i >> 5;
        int b = mBase + r;
        int j = jBase + jj;
        float ghr = S[r * S_STRIDE + jj] + bias_h[j];
        float ghz = S[r * S_STRIDE + 32 + jj] + bias_h[HID + j];
        float ghn = S[r * S_STRIDE + 64 + jj] + bias_h[2 * HID + j];
        float gir, giz, gin;
        if (MODE == 1) {
            gir = bih1[j];
            giz = bih1[HID + j];
            gin = bih1[2 * HID + j];
#pragma unroll
            for (int k = 0; k < 8; ++k) {
                float xv = xs[r * 8 + k];
                gir += xv * w1[jj * 8 + k];
                giz += xv * w1[(32 + jj) * 8 + k];
                gin += xv * w1[(64 + jj) * 8 + k];
            }
        } else {
            const float* gp = gi_scr + (size_t)b * G3;
            gir = gp[j];
            giz = gp[HID + j];
            gin = gp[2 * HID + j];
        }
        float rg = 1.f / (1.f + __expf(-(gir + ghr)));
        float zg = 1.f / (1.f + __expf(-(giz + ghz)));
        float ng = tanhf(gin + rg * ghn);
        float hold = hf[(size_t)b * HID + j];
        float hnew = (1.f - zg) * ng + zg * hold;
        hf[(size_t)b * HID + j] = hnew;
        bf16 hi = __float2bfloat16(hnew);
        out_hi[(size_t)b * HID + j] = hi;
        out_lo[(size_t)b * HID + j] = __float2bfloat16(hnew - __bfloat162float(hi));
    }
}

__global__ void __launch_bounds__(256) y_kernel(
    const float* __restrict__ hf, const float* __restrict__ Wout,
    const float* __restrict__ bout, float* __restrict__ out,
    float* __restrict__ ybuf, int t) {
    int wid = threadIdx.x >> 5, lane = threadIdx.x & 31;
    int b = blockIdx.x * 8 + wid;
    const float* hr = hf + (size_t)b * HID;
    float p[NOUT] = {0.f, 0.f, 0.f, 0.f, 0.f};
    for (int j = lane; j < HID; j += 32) {
        float hv = hr[j];
#pragma unroll
        for (int o = 0; o < NOUT; ++o) p[o] += hv * Wout[o * HID + j];
    }
#pragma unroll
    for (int o = 0; o < NOUT; ++o)
#pragma unroll
        for (int off = 16; off; off >>= 1)
            p[o] += __shfl_down_sync(0xffffffffu, p[o], off);
    if (lane == 0) {
#pragma unroll
        for (int o = 0; o < NOUT; ++o) {
            float v = p[o] + bout[o];
            out[(size_t)b * (T_STEPS * NOUT) + t * NOUT + o] = v;
            ybuf[b * NOUT + o] = v;
        }
    }
}

__global__ void split_kernel(const float* __restrict__ src, float* __restrict__ fdst,
                             bf16* __restrict__ hi, bf16* __restrict__ lo, int n) {
    int i = blockIdx.x * blockDim.x + threadIdx.x;
    if (i < n) {
        float v = src[i];
        if (fdst) fdst[i] = v;
        bf16 h = __float2bfloat16(v);
        hi[i] = h;
        lo[i] = __float2bfloat16(v - __bfloat162float(h));
    }
}

__global__ void copy_kernel(const float* __restrict__ src, float* __restrict__ dst, int n) {
    int i = blockIdx.x * blockDim.x + threadIdx.x;
    if (i < n) dst[i] = src[i];
}

extern "C" void kernel_launch(void* const* d_in, const int* in_sizes, int n_in,
                              void* d_out, int out_size) {
    (void)in_sizes; (void)n_in; (void)out_size;
    const float* cmds = (const float*)d_in[1];
    const float* y0 = (const float*)d_in[2];
    const float* h01 = (const float*)d_in[3];
    const float* h02 = (const float*)d_in[4];
    const float* Wih1 = (const float*)d_in[5];
    const float* Whh1 = (const float*)d_in[6];
    const float* bih1 = (const float*)d_in[7];
    const float* bhh1 = (const float*)d_in[8];
    const float* Wih2 = (const float*)d_in[9];
    const float* Whh2 = (const float*)d_in[10];
    const float* bih2 = (const float*)d_in[11];
    const float* bhh2 = (const float*)d_in[12];
    const float* Wout = (const float*)d_in[13];
    const float* bout = (const float*)d_in[14];
    float* out = (float*)d_out;

    void* p;
    float *h1f, *h2f, *gi, *ybuf;
    bf16 *h1hi, *h1lo, *h2hi, *h2lo;
    bf16 *whh1hi, *whh1lo, *wih2hi, *wih2lo, *whh2hi, *whh2lo;
    cudaGetSymbolAddress(&p, g_h1f); h1f = (float*)p;
    cudaGetSymbolAddress(&p, g_h2f); h2f = (float*)p;
    cudaGetSymbolAddress(&p, g_gi); gi = (float*)p;
    cudaGetSymbolAddress(&p, g_y); ybuf = (float*)p;
    cudaGetSymbolAddress(&p, g_h1hi); h1hi = (bf16*)p;
    cudaGetSymbolAddress(&p, g_h1lo); h1lo = (bf16*)p;
    cudaGetSymbolAddress(&p, g_h2hi); h2hi = (bf16*)p;
    cudaGetSymbolAddress(&p, g_h2lo); h2lo = (bf16*)p;
    cudaGetSymbolAddress(&p, g_whh1hi); whh1hi = (bf16*)p;
    cudaGetSymbolAddress(&p, g_whh1lo); whh1lo = (bf16*)p;
    cudaGetSymbolAddress(&p, g_wih2hi); wih2hi = (bf16*)p;
    cudaGetSymbolAddress(&p, g_wih2lo); wih2lo = (bf16*)p;
    cudaGetSymbolAddress(&p, g_whh2hi); whh2hi = (bf16*)p;
    cudaGetSymbolAddress(&p, g_whh2lo); whh2lo = (bf16*)p;

    // idempotent, capture-safe; called unconditionally (no static guards)
    cudaFuncSetAttribute(fused_step<0>, cudaFuncAttributeMaxDynamicSharedMemorySize, SMEM_BYTES);
    cudaFuncSetAttribute(fused_step<1>, cudaFuncAttributeMaxDynamicSharedMemorySize, SMEM_BYTES);
    cudaFuncSetAttribute(fused_step<2>, cudaFuncAttributeMaxDynamicSharedMemorySize, SMEM_BYTES);

    const int NW = G3 * HID;
    split_kernel<<<(NW + 255) / 256, 256>>>(Whh1, nullptr, whh1hi, whh1lo, NW);
    split_kernel<<<(NW + 255) / 256, 256>>>(Wih2, nullptr, wih2hi, wih2lo, NW);
    split_kernel<<<(NW + 255) / 256, 256>>>(Whh2, nullptr, whh2hi, whh2lo, NW);
    const int NS = BATCH * HID;
    split_kernel<<<(NS + 255) / 256, 256>>>(h01, h1f, h1hi, h1lo, NS);
    split_kernel<<<(NS + 255) / 256, 256>>>(h02, h2f, h2hi, h2lo, NS);
    copy_kernel<<<(BATCH * NOUT + 255) / 256, 256>>>(y0, ybuf, BATCH * NOUT);

    dim3 grid(BATCH / MT, HID / JT);
    for (int t = 0; t < T_STEPS; ++t) {
        int cur = t & 1, nxt = (t + 1) & 1;
        bf16* h1hi_c = h1hi + (size_t)cur * NS;
        bf16* h1lo_c = h1lo + (size_t)cur * NS;
        bf16* h1hi_n = h1hi + (size_t)nxt * NS;
        bf16* h1lo_n = h1lo + (size_t)nxt * NS;
        bf16* h2hi_c = h2hi + (size_t)cur * NS;
        bf16* h2lo_c = h2lo + (size_t)cur * NS;
        bf16* h2hi_n = h2hi + (size_t)nxt * NS;
        bf16* h2lo_n = h2lo + (size_t)nxt * NS;
        const float* cmd_t = cmds + (size_t)t * BATCH * NCMD;

        // layer 1: gh1 = h1 @ W_hh1^T (MMA), gi1 from x (K=8, epilogue), GRU
        fused_step<1><<<grid, 256, SMEM_BYTES>>>(
            h1hi_c, h1lo_c, whh1hi, whh1lo, bhh1, nullptr, nullptr,
            h1f, h1hi_n, h1lo_n, ybuf, cmd_t, Wih1, bih1);
        // layer 2 gi: gi2 = h1_new @ W_ih2^T + b_ih2 -> scratch
        fused_step<0><<<grid, 256, SMEM_BYTES>>>(
            h1hi_n, h1lo_n, wih2hi, wih2lo, bih2, nullptr, gi,
            nullptr, nullptr, nullptr, nullptr, nullptr, nullptr, nullptr);
        // layer 2: gh2 = h2 @ W_hh2^T (MMA), gi from scratch, GRU
        fused_step<2><<<grid, 256, SMEM_BYTES>>>(
            h2hi_c, h2lo_c, whh2hi, whh2lo, bhh2, gi, nullptr,
            h2f, h2hi_n, h2lo_n, nullptr, nullptr, nullptr, nullptr);
        // y = h2 @ W_out^T + b_out  (fp32 exact)
        y_kernel<<<BATCH / 8, 256>>>(h2f, Wout, bout, out, ybuf, t);
    }
}

// round 6
// speedup vs baseline: 1.0543x; 1.0543x over previous
#include <cuda_runtime.h>
#include <cuda_bf16.h>
#include <cstdint>
#include <cstddef>

#define BATCH 2048
#define T_STEPS 128
#define HID 512
#define NCMD 3
#define NOUT 5
#define G3 1536

typedef __nv_bfloat16 bf16;

#define MT 128
#define JT 32
#define NTILE 96
#define KC 32
#define NCHUNK (HID / KC)   // 16
#define KPAD 40             // bf16 elems per row (80B) -> conflict-free ldmatrix
#define A_BYTES (MT * KPAD * 2)                  // 10240
#define B_BYTES (NTILE * KPAD * 2)               // 7680
#define STAGE_BYTES (2 * A_BYTES + 2 * B_BYTES)  // 35840
#define NSTAGE 3
#define STAGES_BYTES (NSTAGE * STAGE_BYTES)      // 107520
#define C1_OFF STAGES_BYTES                      // gi tile (merged kernel)
#define S_STRIDE 100
#define S_BYTES (MT * S_STRIDE * 4)              // 51200
#define XS_OFF (C1_OFF + S_BYTES)                // xs for MODE1 (in C1 region? no: see below)
#define SMEM_TOTAL (C1_OFF + S_BYTES + 4096 + 3072)  // 165888

__device__ float g_h1f[BATCH * HID];
__device__ float g_h2f[BATCH * HID];
__device__ bf16 g_h1hi[2][BATCH * HID];
__device__ bf16 g_h1lo[2][BATCH * HID];
__device__ bf16 g_h2hi[2][BATCH * HID];
__device__ bf16 g_h2lo[2][BATCH * HID];
__device__ bf16 g_whh1hi[G3 * HID];
__device__ bf16 g_whh1lo[G3 * HID];
__device__ bf16 g_wih2hi[G3 * HID];
__device__ bf16 g_wih2lo[G3 * HID];
__device__ bf16 g_whh2hi[G3 * HID];
__device__ bf16 g_whh2lo[G3 * HID];
__device__ float g_y[BATCH * NOUT];

__device__ __forceinline__ void cp16(uint32_t dst, const void* src) {
    asm volatile("cp.async.cg.shared.global [%0], [%1], 16;\n" ::"r"(dst), "l"(src));
}
__device__ __forceinline__ void ldsm4(uint32_t* r, uint32_t addr) {
    asm volatile("ldmatrix.sync.aligned.m8n8.x4.shared.b16 {%0,%1,%2,%3}, [%4];\n"
                 : "=r"(r[0]), "=r"(r[1]), "=r"(r[2]), "=r"(r[3]) : "r"(addr));
}
__device__ __forceinline__ void mma16816(float* c, const uint32_t* a, const uint32_t* b) {
    asm volatile(
        "mma.sync.aligned.m16n8k16.row.col.f32.bf16.bf16.f32 "
        "{%0,%1,%2,%3}, {%4,%5,%6,%7}, {%8,%9}, {%0,%1,%2,%3};\n"
        : "+f"(c[0]), "+f"(c[1]), "+f"(c[2]), "+f"(c[3])
        : "r"(a[0]), "r"(a[1]), "r"(a[2]), "r"(a[3]), "r"(b[0]), "r"(b[1]));
}

// Full K=512 GEMM mainloop: C(128x96) += A(128x512)@W(96rows x512)^T in bf16
// hi/lo 3-pass split. acc must be zeroed by caller. One barrier per chunk,
// 3-stage cp.async pipeline, ldmatrix fragment feed.
__device__ __forceinline__ void run_gemm(
    uint32_t smem_u32, int tid, int mBase, int jBase,
    const bf16* __restrict__ Ahi, const bf16* __restrict__ Alo,
    const bf16* __restrict__ Whi, const bf16* __restrict__ Wlo,
    float acc[2][6][4]) {
    const int lane = tid & 31;
    const int wid = tid >> 5;
    const int warpM = wid & 3;
    const int warpN = wid >> 2;

    // per-thread fixed gmem sources / smem dst offsets (7 x 16B per chunk)
    const bf16* gsrc[7];
    uint32_t sdst[7];
#pragma unroll
    for (int it = 0; it < 7; ++it) {
        int i = tid + it * 256;
        if (i < 1024) {  // A hi/lo: 512 x 16B each
            const bf16* Ab = (i < 512) ? Ahi : Alo;
            uint32_t base = (i < 512) ? 0u : (uint32_t)A_BYTES;
            int rr = i & 511;
            int r = rr >> 2, c4 = rr & 3;
            gsrc[it] = Ab + (size_t)(mBase + r) * HID + c4 * 8;
            sdst[it] = base + r * (KPAD * 2) + c4 * 16;
        } else {  // B hi/lo: 384 x 16B each
            int ii = i - 1024;
            const bf16* Wb = (ii < 384) ? Whi : Wlo;
            uint32_t base = 2 * A_BYTES + ((ii < 384) ? 0u : (uint32_t)B_BYTES);
            int rr = (ii < 384) ? ii : (ii - 384);
            int r = rr >> 2, c4 = rr & 3;
            int wrow = (r >> 5) * HID + jBase + (r & 31);
            gsrc[it] = Wb + (size_t)wrow * HID + c4 * 8;
            sdst[it] = base + r * (KPAD * 2) + c4 * 16;
        }
    }

    // ldmatrix element offsets (bf16 units), kb-independent parts
    uint32_t aoff[2], boff[3];
#pragma unroll
    for (int mt = 0; mt < 2; ++mt)
        aoff[mt] = (uint32_t)((warpM * 32 + mt * 16 + (lane & 15)) * KPAD + (lane >> 4) * 8);
#pragma unroll
    for (int p = 0; p < 3; ++p)
        boff[p] = (uint32_t)((warpN * 48 + p * 16 + (lane & 7) + ((lane & 16) ? 8 : 0)) * KPAD +
                             ((lane & 8) ? 8 : 0));

    // prologue: chunks 0,1
#pragma unroll
    for (int s = 0; s < 2; ++s) {
        uint32_t st = smem_u32 + s * STAGE_BYTES;
        int k0 = s * KC;
#pragma unroll
        for (int it = 0; it < 7; ++it) cp16(st + sdst[it], gsrc[it] + k0);
        asm volatile("cp.async.commit_group;\n");
    }

#pragma unroll 1
    for (int c = 0; c < NCHUNK; ++c) {
        if (c == NCHUNK - 1)
            asm volatile("cp.async.wait_group 0;\n");
        else
            asm volatile("cp.async.wait_group 1;\n");
        __syncthreads();
        if (c + 2 < NCHUNK) {
            uint32_t st = smem_u32 + ((c + 2) % NSTAGE) * STAGE_BYTES;
            int k0 = (c + 2) * KC;
#pragma unroll
            for (int it = 0; it < 7; ++it) cp16(st + sdst[it], gsrc[it] + k0);
            asm volatile("cp.async.commit_group;\n");
        }
        uint32_t cur = smem_u32 + (c % NSTAGE) * STAGE_BYTES;
        uint32_t sAh = cur;
        uint32_t sAl = cur + A_BYTES;
        uint32_t sBh = cur + 2 * A_BYTES;
        uint32_t sBl = cur + 2 * A_BYTES + B_BYTES;
#pragma unroll
        for (int kb = 0; kb < KC; kb += 16) {
            uint32_t a_hi[2][4], a_lo[2][4], b_hi[6][2], b_lo[6][2];
#pragma unroll
            for (int mt = 0; mt < 2; ++mt) ldsm4(&a_hi[mt][0], sAh + (aoff[mt] + kb) * 2);
#pragma unroll
            for (int p = 0; p < 3; ++p) ldsm4(&b_hi[2 * p][0], sBh + (boff[p] + kb) * 2);
#pragma unroll
            for (int mt = 0; mt < 2; ++mt)
#pragma unroll
                for (int nt = 0; nt < 6; ++nt) mma16816(acc[mt][nt], a_hi[mt], b_hi[nt]);
#pragma unroll
            for (int p = 0; p < 3; ++p) ldsm4(&b_lo[2 * p][0], sBl + (boff[p] + kb) * 2);
#pragma unroll
            for (int mt = 0; mt < 2; ++mt)
#pragma unroll
                for (int nt = 0; nt < 6; ++nt) mma16816(acc[mt][nt], a_hi[mt], b_lo[nt]);
#pragma unroll
            for (int mt = 0; mt < 2; ++mt) ldsm4(&a_lo[mt][0], sAl + (aoff[mt] + kb) * 2);
#pragma unroll
            for (int mt = 0; mt < 2; ++mt)
#pragma unroll
                for (int nt = 0; nt < 6; ++nt) mma16816(acc[mt][nt], a_lo[mt], b_hi[nt]);
        }
    }
    __syncthreads();  // all reads of last stage done before smem reuse
}

__device__ __forceinline__ void stash_acc(float* S, float acc[2][6][4], int tid) {
    const int lane = tid & 31;
    const int wid = tid >> 5;
    const int warpM = wid & 3, warpN = wid >> 2;
    const int g = lane >> 2, q = lane & 3;
#pragma unroll
    for (int mt = 0; mt < 2; ++mt)
#pragma unroll
        for (int nt = 0; nt < 6; ++nt) {
            int r0 = warpM * 32 + mt * 16 + g;
            int cc = warpN * 48 + nt * 8 + q * 2;
            S[r0 * S_STRIDE + cc] = acc[mt][nt][0];
            S[r0 * S_STRIDE + cc + 1] = acc[mt][nt][1];
            S[(r0 + 8) * S_STRIDE + cc] = acc[mt][nt][2];
            S[(r0 + 8) * S_STRIDE + cc + 1] = acc[mt][nt][3];
        }
}

// Layer-1 kernel: gh1 = h1@Whh1^T (MMA), gi1 from x=[y,cmd] (K=8 scalar), GRU.
__global__ void __launch_bounds__(256) l1_kernel(
    const bf16* __restrict__ Ahi, const bf16* __restrict__ Alo,
    const bf16* __restrict__ Whi, const bf16* __restrict__ Wlo,
    const float* __restrict__ bhh, float* __restrict__ hf,
    bf16* __restrict__ out_hi, bf16* __restrict__ out_lo,
    const float* __restrict__ ybuf, const float* __restrict__ cmd_t,
    const float* __restrict__ Wih1, const float* __restrict__ bih) {
    extern __shared__ char smem[];
    uint32_t smem_u32 = (uint32_t)__cvta_generic_to_shared(smem);
    const int tid = threadIdx.x;
    const int mBase = blockIdx.x * MT;
    const int jBase = blockIdx.y * JT;

    float acc[2][6][4];
#pragma unroll
    for (int a = 0; a < 2; ++a)
#pragma unroll
        for (int b = 0; b < 6; ++b)
#pragma unroll
            for (int e = 0; e < 4; ++e) acc[a][b][e] = 0.f;

    run_gemm(smem_u32, tid, mBase, jBase, Ahi, Alo, Whi, Wlo, acc);

    float* S = (float*)smem;  // stage region reused
    stash_acc(S, acc, tid);
    float* xs = (float*)(smem + 51200);  // [128][8]
    float* w1 = (float*)(smem + 55296);  // [96][8]
    for (int i = tid; i < MT * 8; i += 256) {
        int r = i >> 3, k = i & 7;
        xs[i] = (k < NOUT) ? ybuf[(mBase + r) * NOUT + k]
                           : cmd_t[(size_t)(mBase + r) * NCMD + (k - NOUT)];
    }
    for (int i = tid; i < NTILE * 8; i += 256) {
        int n = i >> 3, k = i & 7;
        int wr = (n >> 5) * HID + jBase + (n & 31);
        w1[i] = Wih1[wr * 8 + k];
    }
    __syncthreads();

    for (int i = tid; i < MT * JT; i += 256) {
        int jj = i & 31, r = i >> 5;
        int b = mBase + r;
        int j = jBase + jj;
        float ghr = S[r * S_STRIDE + jj] + bhh[j];
        float ghz = S[r * S_STRIDE + 32 + jj] + bhh[HID + j];
        float ghn = S[r * S_STRIDE + 64 + jj] + bhh[2 * HID + j];
        float gir = bih[j], giz = bih[HID + j], gin = bih[2 * HID + j];
#pragma unroll
        for (int k = 0; k < 8; ++k) {
            float xv = xs[r * 8 + k];
            gir += xv * w1[jj * 8 + k];
            giz += xv * w1[(32 + jj) * 8 + k];
            gin += xv * w1[(64 + jj) * 8 + k];
        }
        float rg = 1.f / (1.f + __expf(-(gir + ghr)));
        float zg = 1.f / (1.f + __expf(-(giz + ghz)));
        float ng = tanhf(gin + rg * ghn);
        float hold = hf[(size_t)b * HID + j];
        float hnew = (1.f - zg) * ng + zg * hold;
        hf[(size_t)b * HID + j] = hnew;
        bf16 hi = __float2bfloat16(hnew);
        out_hi[(size_t)b * HID + j] = hi;
        out_lo[(size_t)b * HID + j] = __float2bfloat16(hnew - __bfloat162float(hi));
    }
}

// Layer-2 kernel (merged): gi2 = h1_new@Wih2^T (GEMM1 -> smem), gh2 = h2@Whh2^T
// (GEMM2), then fused GRU update. No global scratch.
__global__ void __launch_bounds__(256) l2_kernel(
    const bf16* __restrict__ A1hi, const bf16* __restrict__ A1lo,  // h1_new
    const bf16* __restrict__ Wihi, const bf16* __restrict__ Wilo,  // W_ih2
    const bf16* __restrict__ A2hi, const bf16* __restrict__ A2lo,  // h2_old
    const bf16* __restrict__ Whhi, const bf16* __restrict__ Whlo,  // W_hh2
    const float* __restrict__ bih, const float* __restrict__ bhh,
    float* __restrict__ hf, bf16* __restrict__ out_hi, bf16* __restrict__ out_lo) {
    extern __shared__ char smem[];
    uint32_t smem_u32 = (uint32_t)__cvta_generic_to_shared(smem);
    const int tid = threadIdx.x;
    const int mBase = blockIdx.x * MT;
    const int jBase = blockIdx.y * JT;

    float acc[2][6][4];
#pragma unroll
    for (int a = 0; a < 2; ++a)
#pragma unroll
        for (int b = 0; b < 6; ++b)
#pragma unroll
            for (int e = 0; e < 4; ++e) acc[a][b][e] = 0.f;

    // GEMM1: gi2
    run_gemm(smem_u32, tid, mBase, jBase, A1hi, A1lo, Wihi, Wilo, acc);
    float* C1 = (float*)(smem + C1_OFF);
    stash_acc(C1, acc, tid);
    __syncthreads();

    // GEMM2: gh2
#pragma unroll
    for (int a = 0; a < 2; ++a)
#pragma unroll
        for (int b = 0; b < 6; ++b)
#pragma unroll
            for (int e = 0; e < 4; ++e) acc[a][b][e] = 0.f;
    run_gemm(smem_u32, tid, mBase, jBase, A2hi, A2lo, Whhi, Whlo, acc);
    float* S = (float*)smem;
    stash_acc(S, acc, tid);
    __syncthreads();

    for (int i = tid; i < MT * JT; i += 256) {
        int jj = i & 31, r = i >> 5;
        int b = mBase + r;
        int j = jBase + jj;
        float ghr = S[r * S_STRIDE + jj] + bhh[j];
        float ghz = S[r * S_STRIDE + 32 + jj] + bhh[HID + j];
        float ghn = S[r * S_STRIDE + 64 + jj] + bhh[2 * HID + j];
        float gir = C1[r * S_STRIDE + jj] + bih[j];
        float giz = C1[r * S_STRIDE + 32 + jj] + bih[HID + j];
        float gin = C1[r * S_STRIDE + 64 + jj] + bih[2 * HID + j];
        float rg = 1.f / (1.f + __expf(-(gir + ghr)));
        float zg = 1.f / (1.f + __expf(-(giz + ghz)));
        float ng = tanhf(gin + rg * ghn);
        float hold = hf[(size_t)b * HID + j];
        float hnew = (1.f - zg) * ng + zg * hold;
        hf[(size_t)b * HID + j] = hnew;
        bf16 hi = __float2bfloat16(hnew);
        out_hi[(size_t)b * HID + j] = hi;
        out_lo[(size_t)b * HID + j] = __float2bfloat16(hnew - __bfloat162float(hi));
    }
}

__global__ void __launch_bounds__(256) y_kernel(
    const float* __restrict__ hf, const float* __restrict__ Wout,
    const float* __restrict__ bout, float* __restrict__ out,
    float* __restrict__ ybuf, int t) {
    int wid = threadIdx.x >> 5, lane = threadIdx.x & 31;
    int b = blockIdx.x * 8 + wid;
    const float* hr = hf + (size_t)b * HID;
    float p[NOUT] = {0.f, 0.f, 0.f, 0.f, 0.f};
    for (int j = lane; j < HID; j += 32) {
        float hv = hr[j];
#pragma unroll
        for (int o = 0; o < NOUT; ++o) p[o] += hv * Wout[o * HID + j];
    }
#pragma unroll
    for (int o = 0; o < NOUT; ++o)
#pragma unroll
        for (int off = 16; off; off >>= 1)
            p[o] += __shfl_down_sync(0xffffffffu, p[o], off);
    if (lane == 0) {
#pragma unroll
        for (int o = 0; o < NOUT; ++o) {
            float v = p[o] + bout[o];
            out[(size_t)b * (T_STEPS * NOUT) + t * NOUT + o] = v;
            ybuf[b * NOUT + o] = v;
        }
    }
}

__global__ void split_kernel(const float* __restrict__ src, float* __restrict__ fdst,
                             bf16* __restrict__ hi, bf16* __restrict__ lo, int n) {
    int i = blockIdx.x * blockDim.x + threadIdx.x;
    if (i < n) {
        float v = src[i];
        if (fdst) fdst[i] = v;
        bf16 h = __float2bfloat16(v);
        hi[i] = h;
        lo[i] = __float2bfloat16(v - __bfloat162float(h));
    }
}

__global__ void copy_kernel(const float* __restrict__ src, float* __restrict__ dst, int n) {
    int i = blockIdx.x * blockDim.x + threadIdx.x;
    if (i < n) dst[i] = src[i];
}

extern "C" void kernel_launch(void* const* d_in, const int* in_sizes, int n_in,
                              void* d_out, int out_size) {
    (void)in_sizes; (void)n_in; (void)out_size;
    const float* cmds = (const float*)d_in[1];
    const float* y0 = (const float*)d_in[2];
    const float* h01 = (const float*)d_in[3];
    const float* h02 = (const float*)d_in[4];
    const float* Wih1 = (const float*)d_in[5];
    const float* Whh1 = (const float*)d_in[6];
    const float* bih1 = (const float*)d_in[7];
    const float* bhh1 = (const float*)d_in[8];
    const float* Wih2 = (const float*)d_in[9];
    const float* Whh2 = (const float*)d_in[10];
    const float* bih2 = (const float*)d_in[11];
    const float* bhh2 = (const float*)d_in[12];
    const float* Wout = (const float*)d_in[13];
    const float* bout = (const float*)d_in[14];
    float* out = (float*)d_out;

    void* p;
    float *h1f, *h2f, *ybuf;
    bf16 *h1hi, *h1lo, *h2hi, *h2lo;
    bf16 *whh1hi, *whh1lo, *wih2hi, *wih2lo, *whh2hi, *whh2lo;
    cudaGetSymbolAddress(&p, g_h1f); h1f = (float*)p;
    cudaGetSymbolAddress(&p, g_h2f); h2f = (float*)p;
    cudaGetSymbolAddress(&p, g_y); ybuf = (float*)p;
    cudaGetSymbolAddress(&p, g_h1hi); h1hi = (bf16*)p;
    cudaGetSymbolAddress(&p, g_h1lo); h1lo = (bf16*)p;
    cudaGetSymbolAddress(&p, g_h2hi); h2hi = (bf16*)p;
    cudaGetSymbolAddress(&p, g_h2lo); h2lo = (bf16*)p;
    cudaGetSymbolAddress(&p, g_whh1hi); whh1hi = (bf16*)p;
    cudaGetSymbolAddress(&p, g_whh1lo); whh1lo = (bf16*)p;
    cudaGetSymbolAddress(&p, g_wih2hi); wih2hi = (bf16*)p;
    cudaGetSymbolAddress(&p, g_wih2lo); wih2lo = (bf16*)p;
    cudaGetSymbolAddress(&p, g_whh2hi); whh2hi = (bf16*)p;
    cudaGetSymbolAddress(&p, g_whh2lo); whh2lo = (bf16*)p;

    cudaFuncSetAttribute(l1_kernel, cudaFuncAttributeMaxDynamicSharedMemorySize, SMEM_TOTAL);
    cudaFuncSetAttribute(l2_kernel, cudaFuncAttributeMaxDynamicSharedMemorySize, SMEM_TOTAL);

    const int NW = G3 * HID;
    split_kernel<<<(NW + 255) / 256, 256>>>(Whh1, nullptr, whh1hi, whh1lo, NW);
    split_kernel<<<(NW + 255) / 256, 256>>>(Wih2, nullptr, wih2hi, wih2lo, NW);
    split_kernel<<<(NW + 255) / 256, 256>>>(Whh2, nullptr, whh2hi, whh2lo, NW);
    const int NS = BATCH * HID;
    split_kernel<<<(NS + 255) / 256, 256>>>(h01, h1f, h1hi, h1lo, NS);
    split_kernel<<<(NS + 255) / 256, 256>>>(h02, h2f, h2hi, h2lo, NS);
    copy_kernel<<<(BATCH * NOUT + 255) / 256, 256>>>(y0, ybuf, BATCH * NOUT);

    dim3 grid(BATCH / MT, HID / JT);
    for (int t = 0; t < T_STEPS; ++t) {
        int cur = t & 1, nxt = (t + 1) & 1;
        bf16* h1hi_c = h1hi + (size_t)cur * NS;
        bf16* h1lo_c = h1lo + (size_t)cur * NS;
        bf16* h1hi_n = h1hi + (size_t)nxt * NS;
        bf16* h1lo_n = h1lo + (size_t)nxt * NS;
        bf16* h2hi_c = h2hi + (size_t)cur * NS;
        bf16* h2lo_c = h2lo + (size_t)cur * NS;
        bf16* h2hi_n = h2hi + (size_t)nxt * NS;
        bf16* h2lo_n = h2lo + (size_t)nxt * NS;
        const float* cmd_t = cmds + (size_t)t * BATCH * NCMD;

        l1_kernel<<<grid, 256, SMEM_TOTAL>>>(
            h1hi_c, h1lo_c, whh1hi, whh1lo, bhh1,
            h1f, h1hi_n, h1lo_n, ybuf, cmd_t, Wih1, bih1);
        l2_kernel<<<grid, 256, SMEM_TOTAL>>>(
            h1hi_n, h1lo_n, wih2hi, wih2lo,
            h2hi_c, h2lo_c, whh2hi, whh2lo,
            bih2, bhh2, h2f, h2hi_n, h2lo_n);
        y_kernel<<<BATCH / 8, 256>>>(h2f, Wout, bout, out, ybuf, t);
    }
}

// round 7
// speedup vs baseline: 1.2418x; 1.1778x over previous
#include <cuda_runtime.h>
#include <cuda_bf16.h>
#include <cstdint>
#include <cstddef>

#define BATCH 2048
#define T_STEPS 128
#define HID 512
#define NCMD 3
#define NOUT 5
#define G3 1536

typedef __nv_bfloat16 bf16;

#define MT 128
#define JT 32
#define NTILE 96
#define KC 16
#define NCHUNK (HID / KC)                        // 32
#define KPAD 24                                  // 48B rows: conflict-free ldmatrix
#define A_BYTES (MT * KPAD * 2)                  // 6144
#define B_BYTES (NTILE * KPAD * 2)               // 4608
#define STAGE_BYTES (2 * A_BYTES + 2 * B_BYTES)  // 21504
#define NSTAGE 3
#define STAGES_BYTES (NSTAGE * STAGE_BYTES)      // 64512
#define SST 97
#define S_BYTES (MT * SST * 4)                   // 49664
#define C1_OFF STAGES_BYTES                      // 64512
#define L1_SMEM STAGES_BYTES                     // 64512 (S/xs/w1 alias stages)
#define L2_SMEM (C1_OFF + S_BYTES)               // 114176 -> 2 blocks/SM

__device__ float g_h1f[BATCH * HID];
__device__ float g_h2f[BATCH * HID];
__device__ bf16 g_h1hi[2][BATCH * HID];
__device__ bf16 g_h1lo[2][BATCH * HID];
__device__ bf16 g_h2hi[2][BATCH * HID];
__device__ bf16 g_h2lo[2][BATCH * HID];
__device__ bf16 g_whh1hi[G3 * HID];
__device__ bf16 g_whh1lo[G3 * HID];
__device__ bf16 g_wih2hi[G3 * HID];
__device__ bf16 g_wih2lo[G3 * HID];
__device__ bf16 g_whh2hi[G3 * HID];
__device__ bf16 g_whh2lo[G3 * HID];
__device__ float g_y[BATCH * NOUT];

__device__ __forceinline__ void cp16(uint32_t dst, const void* src) {
    asm volatile("cp.async.cg.shared.global [%0], [%1], 16;\n" ::"r"(dst), "l"(src));
}
__device__ __forceinline__ void ldsm4(uint32_t* r, uint32_t addr) {
    asm volatile("ldmatrix.sync.aligned.m8n8.x4.shared.b16 {%0,%1,%2,%3}, [%4];\n"
                 : "=r"(r[0]), "=r"(r[1]), "=r"(r[2]), "=r"(r[3]) : "r"(addr));
}
__device__ __forceinline__ void mma16816(float* c, const uint32_t* a, const uint32_t* b) {
    asm volatile(
        "mma.sync.aligned.m16n8k16.row.col.f32.bf16.bf16.f32 "
        "{%0,%1,%2,%3}, {%4,%5,%6,%7}, {%8,%9}, {%0,%1,%2,%3};\n"
        : "+f"(c[0]), "+f"(c[1]), "+f"(c[2]), "+f"(c[3])
        : "r"(a[0]), "r"(a[1]), "r"(a[2]), "r"(a[3]), "r"(b[0]), "r"(b[1]));
}

// K=512 GEMM mainloop, C(128x96) in bf16 hi/lo 3-pass split.
// 32 chunks of K=16, 3-stage cp.async pipeline, 1 barrier/chunk.
__device__ __forceinline__ void run_gemm(
    uint32_t smem_u32, int tid, int mBase, int jBase,
    const bf16* __restrict__ Ahi, const bf16* __restrict__ Alo,
    const bf16* __restrict__ Whi, const bf16* __restrict__ Wlo,
    float acc[2][6][4]) {
    const int lane = tid & 31;
    const int wid = tid >> 5;
    const int warpM = wid & 3;
    const int warpN = wid >> 2;

    // per-thread 16B transfer slots: 896 units / 256 threads = 3.5 -> 4 guarded
    const bf16* gsrc[4];
    uint32_t sdst[4];
    bool gval[4];
#pragma unroll
    for (int it = 0; it < 4; ++it) {
        int i = tid + it * 256;
        gval[it] = (i < 896);
        int u = gval[it] ? i : 0;
        if (u < 512) {  // A hi/lo: 256 units each
            const bf16* Ab = (u < 256) ? Ahi : Alo;
            uint32_t base = (u < 256) ? 0u : (uint32_t)A_BYTES;
            int rr = u & 255;
            int r = rr >> 1, c2 = rr & 1;
            gsrc[it] = Ab + (size_t)(mBase + r) * HID + c2 * 8;
            sdst[it] = base + r * (KPAD * 2) + c2 * 16;
        } else {  // B hi/lo: 192 units each
            int v = u - 512;
            const bf16* Wb = (v < 192) ? Whi : Wlo;
            uint32_t base = 2 * A_BYTES + ((v < 192) ? 0u : (uint32_t)B_BYTES);
            int rr = (v < 192) ? v : (v - 192);
            int r = rr >> 1, c2 = rr & 1;
            int wrow = (r >> 5) * HID + jBase + (r & 31);
            gsrc[it] = Wb + (size_t)wrow * HID + c2 * 8;
            sdst[it] = base + r * (KPAD * 2) + c2 * 16;
        }
    }

    uint32_t aoff[2], boff[3];
#pragma unroll
    for (int mt = 0; mt < 2; ++mt)
        aoff[mt] = (uint32_t)((warpM * 32 + mt * 16 + (lane & 15)) * KPAD + (lane >> 4) * 8);
#pragma unroll
    for (int p = 0; p < 3; ++p)
        boff[p] = (uint32_t)((warpN * 48 + p * 16 + (lane & 7) + ((lane & 16) ? 8 : 0)) * KPAD +
                             ((lane & 8) ? 8 : 0));

#pragma unroll
    for (int s = 0; s < 2; ++s) {
        uint32_t st = smem_u32 + s * STAGE_BYTES;
        int k0 = s * KC;
#pragma unroll
        for (int it = 0; it < 4; ++it)
            if (gval[it]) cp16(st + sdst[it], gsrc[it] + k0);
        asm volatile("cp.async.commit_group;\n");
    }

#pragma unroll 1
    for (int c = 0; c < NCHUNK; ++c) {
        if (c == NCHUNK - 1)
            asm volatile("cp.async.wait_group 0;\n");
        else
            asm volatile("cp.async.wait_group 1;\n");
        __syncthreads();
        if (c + 2 < NCHUNK) {
            uint32_t st = smem_u32 + ((c + 2) % NSTAGE) * STAGE_BYTES;
            int k0 = (c + 2) * KC;
#pragma unroll
            for (int it = 0; it < 4; ++it)
                if (gval[it]) cp16(st + sdst[it], gsrc[it] + k0);
            asm volatile("cp.async.commit_group;\n");
        }
        uint32_t cur = smem_u32 + (c % NSTAGE) * STAGE_BYTES;
        uint32_t sAh = cur;
        uint32_t sAl = cur + A_BYTES;
        uint32_t sBh = cur + 2 * A_BYTES;
        uint32_t sBl = cur + 2 * A_BYTES + B_BYTES;

        uint32_t a_hi[2][4], a_lo[2][4], b_hi[6][2], b_lo[6][2];
#pragma unroll
        for (int mt = 0; mt < 2; ++mt) ldsm4(&a_hi[mt][0], sAh + aoff[mt] * 2);
#pragma unroll
        for (int p = 0; p < 3; ++p) ldsm4(&b_hi[2 * p][0], sBh + boff[p] * 2);
#pragma unroll
        for (int mt = 0; mt < 2; ++mt)
#pragma unroll
            for (int nt = 0; nt < 6; ++nt) mma16816(acc[mt][nt], a_hi[mt], b_hi[nt]);
#pragma unroll
        for (int p = 0; p < 3; ++p) ldsm4(&b_lo[2 * p][0], sBl + boff[p] * 2);
#pragma unroll
        for (int mt = 0; mt < 2; ++mt)
#pragma unroll
            for (int nt = 0; nt < 6; ++nt) mma16816(acc[mt][nt], a_hi[mt], b_lo[nt]);
#pragma unroll
        for (int mt = 0; mt < 2; ++mt) ldsm4(&a_lo[mt][0], sAl + aoff[mt] * 2);
#pragma unroll
        for (int mt = 0; mt < 2; ++mt)
#pragma unroll
            for (int nt = 0; nt < 6; ++nt) mma16816(acc[mt][nt], a_lo[mt], b_hi[nt]);
    }
    __syncthreads();
}

__device__ __forceinline__ void stash_acc(float* S, float acc[2][6][4], int tid) {
    const int lane = tid & 31;
    const int wid = tid >> 5;
    const int warpM = wid & 3, warpN = wid >> 2;
    const int g = lane >> 2, q = lane & 3;
#pragma unroll
    for (int mt = 0; mt < 2; ++mt)
#pragma unroll
        for (int nt = 0; nt < 6; ++nt) {
            int r0 = warpM * 32 + mt * 16 + g;
            int cc = warpN * 48 + nt * 8 + q * 2;
            S[r0 * SST + cc] = acc[mt][nt][0];
            S[r0 * SST + cc + 1] = acc[mt][nt][1];
            S[(r0 + 8) * SST + cc] = acc[mt][nt][2];
            S[(r0 + 8) * SST + cc + 1] = acc[mt][nt][3];
        }
}

__global__ void __launch_bounds__(256) l1_kernel(
    const bf16* __restrict__ Ahi, const bf16* __restrict__ Alo,
    const bf16* __restrict__ Whi, const bf16* __restrict__ Wlo,
    const float* __restrict__ bhh, float* __restrict__ hf,
    bf16* __restrict__ out_hi, bf16* __restrict__ out_lo,
    const float* __restrict__ ybuf, const float* __restrict__ cmd_t,
    const float* __restrict__ Wih1, const float* __restrict__ bih) {
    extern __shared__ char smem[];
    uint32_t smem_u32 = (uint32_t)__cvta_generic_to_shared(smem);
    const int tid = threadIdx.x;
    const int mBase = blockIdx.x * MT;
    const int jBase = blockIdx.y * JT;

    float acc[2][6][4];
#pragma unroll
    for (int a = 0; a < 2; ++a)
#pragma unroll
        for (int b = 0; b < 6; ++b)
#pragma unroll
            for (int e = 0; e < 4; ++e) acc[a][b][e] = 0.f;

    run_gemm(smem_u32, tid, mBase, jBase, Ahi, Alo, Whi, Wlo, acc);

    float* S = (float*)smem;             // aliases stages (safe after final sync)
    stash_acc(S, acc, tid);
    float* xs = (float*)(smem + S_BYTES);         // [128][8]
    float* w1 = (float*)(smem + S_BYTES + 4096);  // [96][8]
    for (int i = tid; i < MT * 8; i += 256) {
        int r = i >> 3, k = i & 7;
        xs[i] = (k < NOUT) ? ybuf[(mBase + r) * NOUT + k]
                           : cmd_t[(size_t)(mBase + r) * NCMD + (k - NOUT)];
    }
    for (int i = tid; i < NTILE * 8; i += 256) {
        int n = i >> 3, k = i & 7;
        int wr = (n >> 5) * HID + jBase + (n & 31);
        w1[i] = Wih1[wr * 8 + k];
    }
    __syncthreads();

    for (int i = tid; i < MT * JT; i += 256) {
        int jj = i & 31, r = i >> 5;
        int b = mBase + r;
        int j = jBase + jj;
        float ghr = S[r * SST + jj] + bhh[j];
        float ghz = S[r * SST + 32 + jj] + bhh[HID + j];
        float ghn = S[r * SST + 64 + jj] + bhh[2 * HID + j];
        float gir = bih[j], giz = bih[HID + j], gin = bih[2 * HID + j];
#pragma unroll
        for (int k = 0; k < 8; ++k) {
            float xv = xs[r * 8 + k];
            gir += xv * w1[jj * 8 + k];
            giz += xv * w1[(32 + jj) * 8 + k];
            gin += xv * w1[(64 + jj) * 8 + k];
        }
        float rg = 1.f / (1.f + __expf(-(gir + ghr)));
        float zg = 1.f / (1.f + __expf(-(giz + ghz)));
        float ng = tanhf(gin + rg * ghn);
        float hold = hf[(size_t)b * HID + j];
        float hnew = (1.f - zg) * ng + zg * hold;
        hf[(size_t)b * HID + j] = hnew;
        bf16 hi = __float2bfloat16(hnew);
        out_hi[(size_t)b * HID + j] = hi;
        out_lo[(size_t)b * HID + j] = __float2bfloat16(hnew - __bfloat162float(hi));
    }
}

__global__ void __launch_bounds__(256) l2_kernel(
    const bf16* __restrict__ A1hi, const bf16* __restrict__ A1lo,  // h1_new
    const bf16* __restrict__ Wihi, const bf16* __restrict__ Wilo,  // W_ih2
    const bf16* __restrict__ A2hi, const bf16* __restrict__ A2lo,  // h2_old
    const bf16* __restrict__ Whhi, const bf16* __restrict__ Whlo,  // W_hh2
    const float* __restrict__ bih, const float* __restrict__ bhh,
    float* __restrict__ hf, bf16* __restrict__ out_hi, bf16* __restrict__ out_lo) {
    extern __shared__ char smem[];
    uint32_t smem_u32 = (uint32_t)__cvta_generic_to_shared(smem);
    const int tid = threadIdx.x;
    const int mBase = blockIdx.x * MT;
    const int jBase = blockIdx.y * JT;

    float acc[2][6][4];
#pragma unroll
    for (int a = 0; a < 2; ++a)
#pragma unroll
        for (int b = 0; b < 6; ++b)
#pragma unroll
            for (int e = 0; e < 4; ++e) acc[a][b][e] = 0.f;

    run_gemm(smem_u32, tid, mBase, jBase, A1hi, A1lo, Wihi, Wilo, acc);
    float* C1 = (float*)(smem + C1_OFF);  // survives GEMM2 (above stages)
    stash_acc(C1, acc, tid);
    __syncthreads();

#pragma unroll
    for (int a = 0; a < 2; ++a)
#pragma unroll
        for (int b = 0; b < 6; ++b)
#pragma unroll
            for (int e = 0; e < 4; ++e) acc[a][b][e] = 0.f;
    run_gemm(smem_u32, tid, mBase, jBase, A2hi, A2lo, Whhi, Whlo, acc);
    float* S = (float*)smem;
    stash_acc(S, acc, tid);
    __syncthreads();

    for (int i = tid; i < MT * JT; i += 256) {
        int jj = i & 31, r = i >> 5;
        int b = mBase + r;
        int j = jBase + jj;
        float ghr = S[r * SST + jj] + bhh[j];
        float ghz = S[r * SST + 32 + jj] + bhh[HID + j];
        float ghn = S[r * SST + 64 + jj] + bhh[2 * HID + j];
        float gir = C1[r * SST + jj] + bih[j];
        float giz = C1[r * SST + 32 + jj] + bih[HID + j];
        float gin = C1[r * SST + 64 + jj] + bih[2 * HID + j];
        float rg = 1.f / (1.f + __expf(-(gir + ghr)));
        float zg = 1.f / (1.f + __expf(-(giz + ghz)));
        float ng = tanhf(gin + rg * ghn);
        float hold = hf[(size_t)b * HID + j];
        float hnew = (1.f - zg) * ng + zg * hold;
        hf[(size_t)b * HID + j] = hnew;
        bf16 hi = __float2bfloat16(hnew);
        out_hi[(size_t)b * HID + j] = hi;
        out_lo[(size_t)b * HID + j] = __float2bfloat16(hnew - __bfloat162float(hi));
    }
}

__global__ void __launch_bounds__(256) y_kernel(
    const float* __restrict__ hf, const float* __restrict__ Wout,
    const float* __restrict__ bout, float* __restrict__ out,
    float* __restrict__ ybuf, int t) {
    int wid = threadIdx.x >> 5, lane = threadIdx.x & 31;
    int b = blockIdx.x * 8 + wid;
    const float* hr = hf + (size_t)b * HID;
    float p[NOUT] = {0.f, 0.f, 0.f, 0.f, 0.f};
    for (int j = lane; j < HID; j += 32) {
        float hv = hr[j];
#pragma unroll
        for (int o = 0; o < NOUT; ++o) p[o] += hv * Wout[o * HID + j];
    }
#pragma unroll
    for (int o = 0; o < NOUT; ++o)
#pragma unroll
        for (int off = 16; off; off >>= 1)
            p[o] += __shfl_down_sync(0xffffffffu, p[o], off);
    if (lane == 0) {
#pragma unroll
        for (int o = 0; o < NOUT; ++o) {
            float v = p[o] + bout[o];
            out[(size_t)b * (T_STEPS * NOUT) + t * NOUT + o] = v;
            ybuf[b * NOUT + o] = v;
        }
    }
}

// single fused init: weight hi/lo splits + state splits + y copy (1 launch)
__global__ void init_kernel(
    const float* __restrict__ Whh1, const float* __restrict__ Wih2,
    const float* __restrict__ Whh2, const float* __restrict__ h01,
    const float* __restrict__ h02, const float* __restrict__ y0,
    bf16* __restrict__ whh1hi, bf16* __restrict__ whh1lo,
    bf16* __restrict__ wih2hi, bf16* __restrict__ wih2lo,
    bf16* __restrict__ whh2hi, bf16* __restrict__ whh2lo,
    float* __restrict__ h1f, float* __restrict__ h2f,
    bf16* __restrict__ h1hi, bf16* __restrict__ h1lo,
    bf16* __restrict__ h2hi, bf16* __restrict__ h2lo,
    float* __restrict__ ybuf) {
    int i = blockIdx.x * blockDim.x + threadIdx.x;
    const int NW = G3 * HID;
    const int NS = BATCH * HID;
    if (i < NW) {
        float v = Whh1[i];
        bf16 h = __float2bfloat16(v);
        whh1hi[i] = h;
        whh1lo[i] = __float2bfloat16(v - __bfloat162float(h));
        v = Wih2[i];
        h = __float2bfloat16(v);
        wih2hi[i] = h;
        wih2lo[i] = __float2bfloat16(v - __bfloat162float(h));
        v = Whh2[i];
        h = __float2bfloat16(v);
        whh2hi[i] = h;
        whh2lo[i] = __float2bfloat16(v - __bfloat162float(h));
    }
    if (i < NS) {
        float v = h01[i];
        h1f[i] = v;
        bf16 h = __float2bfloat16(v);
        h1hi[i] = h;
        h1lo[i] = __float2bfloat16(v - __bfloat162float(h));
        v = h02[i];
        h2f[i] = v;
        h = __float2bfloat16(v);
        h2hi[i] = h;
        h2lo[i] = __float2bfloat16(v - __bfloat162float(h));
    }
    if (i < BATCH * NOUT) ybuf[i] = y0[i];
}

extern "C" void kernel_launch(void* const* d_in, const int* in_sizes, int n_in,
                              void* d_out, int out_size) {
    (void)in_sizes; (void)n_in; (void)out_size;
    const float* cmds = (const float*)d_in[1];
    const float* y0 = (const float*)d_in[2];
    const float* h01 = (const float*)d_in[3];
    const float* h02 = (const float*)d_in[4];
    const float* Wih1 = (const float*)d_in[5];
    const float* Whh1 = (const float*)d_in[6];
    const float* bih1 = (const float*)d_in[7];
    const float* bhh1 = (const float*)d_in[8];
    const float* Wih2 = (const float*)d_in[9];
    const float* Whh2 = (const float*)d_in[10];
    const float* bih2 = (const float*)d_in[11];
    const float* bhh2 = (const float*)d_in[12];
    const float* Wout = (const float*)d_in[13];
    const float* bout = (const float*)d_in[14];
    float* out = (float*)d_out;

    void* p;
    float *h1f, *h2f, *ybuf;
    bf16 *h1hi, *h1lo, *h2hi, *h2lo;
    bf16 *whh1hi, *whh1lo, *wih2hi, *wih2lo, *whh2hi, *whh2lo;
    cudaGetSymbolAddress(&p, g_h1f); h1f = (float*)p;
    cudaGetSymbolAddress(&p, g_h2f); h2f = (float*)p;
    cudaGetSymbolAddress(&p, g_y); ybuf = (float*)p;
    cudaGetSymbolAddress(&p, g_h1hi); h1hi = (bf16*)p;
    cudaGetSymbolAddress(&p, g_h1lo); h1lo = (bf16*)p;
    cudaGetSymbolAddress(&p, g_h2hi); h2hi = (bf16*)p;
    cudaGetSymbolAddress(&p, g_h2lo); h2lo = (bf16*)p;
    cudaGetSymbolAddress(&p, g_whh1hi); whh1hi = (bf16*)p;
    cudaGetSymbolAddress(&p, g_whh1lo); whh1lo = (bf16*)p;
    cudaGetSymbolAddress(&p, g_wih2hi); wih2hi = (bf16*)p;
    cudaGetSymbolAddress(&p, g_wih2lo); wih2lo = (bf16*)p;
    cudaGetSymbolAddress(&p, g_whh2hi); whh2hi = (bf16*)p;
    cudaGetSymbolAddress(&p, g_whh2lo); whh2lo = (bf16*)p;

    cudaFuncSetAttribute(l1_kernel, cudaFuncAttributeMaxDynamicSharedMemorySize, L1_SMEM);
    cudaFuncSetAttribute(l2_kernel, cudaFuncAttributeMaxDynamicSharedMemorySize, L2_SMEM);

    const int NS = BATCH * HID;
    init_kernel<<<(NS + 255) / 256, 256>>>(
        Whh1, Wih2, Whh2, h01, h02, y0,
        whh1hi, whh1lo, wih2hi, wih2lo, whh2hi, whh2lo,
        h1f, h2f, h1hi, h1lo, h2hi, h2lo, ybuf);

    dim3 grid(BATCH / MT, HID / JT);
    for (int t = 0; t < T_STEPS; ++t) {
        int cur = t & 1, nxt = (t + 1) & 1;
        bf16* h1hi_c = h1hi + (size_t)cur * NS;
        bf16* h1lo_c = h1lo + (size_t)cur * NS;
        bf16* h1hi_n = h1hi + (size_t)nxt * NS;
        bf16* h1lo_n = h1lo + (size_t)nxt * NS;
        bf16* h2hi_c = h2hi + (size_t)cur * NS;
        bf16* h2lo_c = h2lo + (size_t)cur * NS;
        bf16* h2hi_n = h2hi + (size_t)nxt * NS;
        bf16* h2lo_n = h2lo + (size_t)nxt * NS;
        const float* cmd_t = cmds + (size_t)t * BATCH * NCMD;

        l1_kernel<<<grid, 256, L1_SMEM>>>(
            h1hi_c, h1lo_c, whh1hi, whh1lo, bhh1,
            h1f, h1hi_n, h1lo_n, ybuf, cmd_t, Wih1, bih1);
        l2_kernel<<<grid, 256, L2_SMEM>>>(
            h1hi_n, h1lo_n, wih2hi, wih2lo,
            h2hi_c, h2lo_c, whh2hi, whh2lo,
            bih2, bhh2, h2f, h2hi_n, h2lo_n);
        y_kernel<<<BATCH / 8, 256>>>(h2f, Wout, bout, out, ybuf, t);
    }
}

// round 8
// speedup vs baseline: 1.2791x; 1.0301x over previous
#include <cuda_runtime.h>
#include <cuda_bf16.h>
#include <cstdint>
#include <cstddef>

#define BATCH 2048
#define T_STEPS 128
#define HID 512
#define NCMD 3
#define NOUT 5
#define G3 1536

typedef __nv_bfloat16 bf16;

#define MT 128
#define JT 32
#define NTILE 96
#define KC 16
#define NCHUNK (HID / KC)                        // 32
#define KPAD 24                                  // 48B rows: conflict-free ldmatrix
#define A_BYTES (MT * KPAD * 2)                  // 6144
#define B_BYTES (NTILE * KPAD * 2)               // 4608
#define STAGE_BYTES (2 * A_BYTES + 2 * B_BYTES)  // 21504
#define NSTAGE 3
#define STAGES_BYTES (NSTAGE * STAGE_BYTES)      // 64512
#define SST 97
#define S_BYTES (MT * SST * 4)                   // 49664
#define C1_OFF STAGES_BYTES                      // 64512
#define L1_SMEM STAGES_BYTES                     // 64512 (S/xs/w1 alias stages)
#define L2_SMEM (C1_OFF + S_BYTES)               // 114176 -> 2 blocks/SM

__device__ float g_h1f[BATCH * HID];
__device__ float g_h2f[BATCH * HID];
__device__ bf16 g_h1hi[2][BATCH * HID];
__device__ bf16 g_h1lo[2][BATCH * HID];
__device__ bf16 g_h2hi[2][BATCH * HID];
__device__ bf16 g_h2lo[2][BATCH * HID];
__device__ bf16 g_whh1hi[G3 * HID];
__device__ bf16 g_whh1lo[G3 * HID];
__device__ bf16 g_wih2hi[G3 * HID];
__device__ bf16 g_wih2lo[G3 * HID];
__device__ bf16 g_whh2hi[G3 * HID];
__device__ bf16 g_whh2lo[G3 * HID];
__device__ float g_y[BATCH * NOUT];

__device__ __forceinline__ void cp16(uint32_t dst, const void* src) {
    asm volatile("cp.async.cg.shared.global [%0], [%1], 16;\n" ::"r"(dst), "l"(src));
}
__device__ __forceinline__ void ldsm4(uint32_t* r, uint32_t addr) {
    asm volatile("ldmatrix.sync.aligned.m8n8.x4.shared.b16 {%0,%1,%2,%3}, [%4];\n"
                 : "=r"(r[0]), "=r"(r[1]), "=r"(r[2]), "=r"(r[3]) : "r"(addr));
}
__device__ __forceinline__ void mma16816(float* c, const uint32_t* a, const uint32_t* b) {
    asm volatile(
        "mma.sync.aligned.m16n8k16.row.col.f32.bf16.bf16.f32 "
        "{%0,%1,%2,%3}, {%4,%5,%6,%7}, {%8,%9}, {%0,%1,%2,%3};\n"
        : "+f"(c[0]), "+f"(c[1]), "+f"(c[2]), "+f"(c[3])
        : "r"(a[0]), "r"(a[1]), "r"(a[2]), "r"(a[3]), "r"(b[0]), "r"(b[1]));
}

// K=512 GEMM mainloop, C(128x96) in bf16 hi/lo 3-pass split.
// 32 chunks of K=16, 3-stage cp.async pipeline, 1 barrier/chunk.
// Pass order (AhBh, AlBh, AhBl) minimizes live registers.
__device__ __forceinline__ void run_gemm(
    uint32_t smem_u32, int tid, int mBase, int jBase,
    const bf16* __restrict__ Ahi, const bf16* __restrict__ Alo,
    const bf16* __restrict__ Whi, const bf16* __restrict__ Wlo,
    float acc[2][6][4]) {
    const int lane = tid & 31;
    const int wid = tid >> 5;
    const int warpM = wid & 3;
    const int warpN = wid >> 2;

    // per-thread 16B transfer slots: 896 units / 256 threads -> 4 guarded
    const bf16* gsrc[4];
    uint32_t sdst[4];
    bool gval[4];
#pragma unroll
    for (int it = 0; it < 4; ++it) {
        int i = tid + it * 256;
        gval[it] = (i < 896);
        int u = gval[it] ? i : 0;
        if (u < 512) {  // A hi/lo: 256 units each
            const bf16* Ab = (u < 256) ? Ahi : Alo;
            uint32_t base = (u < 256) ? 0u : (uint32_t)A_BYTES;
            int rr = u & 255;
            int r = rr >> 1, c2 = rr & 1;
            gsrc[it] = Ab + (size_t)(mBase + r) * HID + c2 * 8;
            sdst[it] = base + r * (KPAD * 2) + c2 * 16;
        } else {  // B hi/lo: 192 units each
            int v = u - 512;
            const bf16* Wb = (v < 192) ? Whi : Wlo;
            uint32_t base = 2 * A_BYTES + ((v < 192) ? 0u : (uint32_t)B_BYTES);
            int rr = (v < 192) ? v : (v - 192);
            int r = rr >> 1, c2 = rr & 1;
            int wrow = (r >> 5) * HID + jBase + (r & 31);
            gsrc[it] = Wb + (size_t)wrow * HID + c2 * 8;
            sdst[it] = base + r * (KPAD * 2) + c2 * 16;
        }
    }

    uint32_t aoff[2], boff[3];
#pragma unroll
    for (int mt = 0; mt < 2; ++mt)
        aoff[mt] = (uint32_t)((warpM * 32 + mt * 16 + (lane & 15)) * KPAD + (lane >> 4) * 8);
#pragma unroll
    for (int p = 0; p < 3; ++p)
        boff[p] = (uint32_t)((warpN * 48 + p * 16 + (lane & 7) + ((lane & 16) ? 8 : 0)) * KPAD +
                             ((lane & 8) ? 8 : 0));

#pragma unroll
    for (int s = 0; s < 2; ++s) {
        uint32_t st = smem_u32 + s * STAGE_BYTES;
        int k0 = s * KC;
#pragma unroll
        for (int it = 0; it < 4; ++it)
            if (gval[it]) cp16(st + sdst[it], gsrc[it] + k0);
        asm volatile("cp.async.commit_group;\n");
    }

#pragma unroll 1
    for (int c = 0; c < NCHUNK; ++c) {
        if (c == NCHUNK - 1)
            asm volatile("cp.async.wait_group 0;\n");
        else
            asm volatile("cp.async.wait_group 1;\n");
        __syncthreads();
        if (c + 2 < NCHUNK) {
            uint32_t st = smem_u32 + ((c + 2) % NSTAGE) * STAGE_BYTES;
            int k0 = (c + 2) * KC;
#pragma unroll
            for (int it = 0; it < 4; ++it)
                if (gval[it]) cp16(st + sdst[it], gsrc[it] + k0);
            asm volatile("cp.async.commit_group;\n");
        }
        uint32_t cur = smem_u32 + (c % NSTAGE) * STAGE_BYTES;
        uint32_t sAh = cur;
        uint32_t sAl = cur + A_BYTES;
        uint32_t sBh = cur + 2 * A_BYTES;
        uint32_t sBl = cur + 2 * A_BYTES + B_BYTES;

        // pass 1: Ahi x Bhi
        uint32_t a_frag[2][4], b_hi[6][2];
#pragma unroll
        for (int mt = 0; mt < 2; ++mt) ldsm4(&a_frag[mt][0], sAh + aoff[mt] * 2);
#pragma unroll
        for (int p = 0; p < 3; ++p) ldsm4(&b_hi[2 * p][0], sBh + boff[p] * 2);
#pragma unroll
        for (int mt = 0; mt < 2; ++mt)
#pragma unroll
            for (int nt = 0; nt < 6; ++nt) mma16816(acc[mt][nt], a_frag[mt], b_hi[nt]);
        // pass 2: Alo x Bhi (reuse a_frag regs for a_lo)
        uint32_t a_lo[2][4];
#pragma unroll
        for (int mt = 0; mt < 2; ++mt) ldsm4(&a_lo[mt][0], sAl + aoff[mt] * 2);
#pragma unroll
        for (int mt = 0; mt < 2; ++mt)
#pragma unroll
            for (int nt = 0; nt < 6; ++nt) mma16816(acc[mt][nt], a_lo[mt], b_hi[nt]);
        // pass 3: Ahi x Blo (b_hi dead; b_lo reuses its regs)
        uint32_t b_lo[6][2];
#pragma unroll
        for (int p = 0; p < 3; ++p) ldsm4(&b_lo[2 * p][0], sBl + boff[p] * 2);
#pragma unroll
        for (int mt = 0; mt < 2; ++mt)
#pragma unroll
            for (int nt = 0; nt < 6; ++nt) mma16816(acc[mt][nt], a_frag[mt], b_lo[nt]);
    }
    __syncthreads();
}

__device__ __forceinline__ void stash_acc(float* S, float acc[2][6][4], int tid) {
    const int lane = tid & 31;
    const int wid = tid >> 5;
    const int warpM = wid & 3, warpN = wid >> 2;
    const int g = lane >> 2, q = lane & 3;
#pragma unroll
    for (int mt = 0; mt < 2; ++mt)
#pragma unroll
        for (int nt = 0; nt < 6; ++nt) {
            int r0 = warpM * 32 + mt * 16 + g;
            int cc = warpN * 48 + nt * 8 + q * 2;
            S[r0 * SST + cc] = acc[mt][nt][0];
            S[r0 * SST + cc + 1] = acc[mt][nt][1];
            S[(r0 + 8) * SST + cc] = acc[mt][nt][2];
            S[(r0 + 8) * SST + cc + 1] = acc[mt][nt][3];
        }
}

__global__ void __launch_bounds__(256, 2) l1_kernel(
    const bf16* __restrict__ Ahi, const bf16* __restrict__ Alo,
    const bf16* __restrict__ Whi, const bf16* __restrict__ Wlo,
    const float* __restrict__ bhh, float* __restrict__ hf,
    bf16* __restrict__ out_hi, bf16* __restrict__ out_lo,
    const float* __restrict__ ybuf, const float* __restrict__ cmd_t,
    const float* __restrict__ Wih1, const float* __restrict__ bih) {
    extern __shared__ char smem[];
    uint32_t smem_u32 = (uint32_t)__cvta_generic_to_shared(smem);
    const int tid = threadIdx.x;
    const int mBase = blockIdx.x * MT;
    const int jBase = blockIdx.y * JT;

    float acc[2][6][4];
#pragma unroll
    for (int a = 0; a < 2; ++a)
#pragma unroll
        for (int b = 0; b < 6; ++b)
#pragma unroll
            for (int e = 0; e < 4; ++e) acc[a][b][e] = 0.f;

    run_gemm(smem_u32, tid, mBase, jBase, Ahi, Alo, Whi, Wlo, acc);

    float* S = (float*)smem;             // aliases stages (safe after final sync)
    stash_acc(S, acc, tid);
    float* xs = (float*)(smem + S_BYTES);         // [128][8]
    float* w1 = (float*)(smem + S_BYTES + 4096);  // [96][8]
    for (int i = tid; i < MT * 8; i += 256) {
        int r = i >> 3, k = i & 7;
        xs[i] = (k < NOUT) ? ybuf[(mBase + r) * NOUT + k]
                           : cmd_t[(size_t)(mBase + r) * NCMD + (k - NOUT)];
    }
    for (int i = tid; i < NTILE * 8; i += 256) {
        int n = i >> 3, k = i & 7;
        int wr = (n >> 5) * HID + jBase + (n & 31);
        w1[i] = Wih1[wr * 8 + k];
    }
    __syncthreads();

    for (int i = tid; i < MT * JT; i += 256) {
        int jj = i & 31, r = i >> 5;
        int b = mBase + r;
        int j = jBase + jj;
        float ghr = S[r * SST + jj] + bhh[j];
        float ghz = S[r * SST + 32 + jj] + bhh[HID + j];
        float ghn = S[r * SST + 64 + jj] + bhh[2 * HID + j];
        float gir = bih[j], giz = bih[HID + j], gin = bih[2 * HID + j];
#pragma unroll
        for (int k = 0; k < 8; ++k) {
            float xv = xs[r * 8 + k];
            gir += xv * w1[jj * 8 + k];
            giz += xv * w1[(32 + jj) * 8 + k];
            gin += xv * w1[(64 + jj) * 8 + k];
        }
        float rg = 1.f / (1.f + __expf(-(gir + ghr)));
        float zg = 1.f / (1.f + __expf(-(giz + ghz)));
        float ng = tanhf(gin + rg * ghn);
        float hold = hf[(size_t)b * HID + j];
        float hnew = (1.f - zg) * ng + zg * hold;
        hf[(size_t)b * HID + j] = hnew;
        bf16 hi = __float2bfloat16(hnew);
        out_hi[(size_t)b * HID + j] = hi;
        out_lo[(size_t)b * HID + j] = __float2bfloat16(hnew - __bfloat162float(hi));
    }
}

__global__ void __launch_bounds__(256, 2) l2_kernel(
    const bf16* __restrict__ A1hi, const bf16* __restrict__ A1lo,  // h1_new
    const bf16* __restrict__ Wihi, const bf16* __restrict__ Wilo,  // W_ih2
    const bf16* __restrict__ A2hi, const bf16* __restrict__ A2lo,  // h2_old
    const bf16* __restrict__ Whhi, const bf16* __restrict__ Whlo,  // W_hh2
    const float* __restrict__ bih, const float* __restrict__ bhh,
    float* __restrict__ hf, bf16* __restrict__ out_hi, bf16* __restrict__ out_lo) {
    extern __shared__ char smem[];
    uint32_t smem_u32 = (uint32_t)__cvta_generic_to_shared(smem);
    const int tid = threadIdx.x;
    const int mBase = blockIdx.x * MT;
    const int jBase = blockIdx.y * JT;

    float acc[2][6][4];
#pragma unroll
    for (int a = 0; a < 2; ++a)
#pragma unroll
        for (int b = 0; b < 6; ++b)
#pragma unroll
            for (int e = 0; e < 4; ++e) acc[a][b][e] = 0.f;

    run_gemm(smem_u32, tid, mBase, jBase, A1hi, A1lo, Wihi, Wilo, acc);
    float* C1 = (float*)(smem + C1_OFF);  // survives GEMM2 (above stages)
    stash_acc(C1, acc, tid);
    __syncthreads();

#pragma unroll
    for (int a = 0; a < 2; ++a)
#pragma unroll
        for (int b = 0; b < 6; ++b)
#pragma unroll
            for (int e = 0; e < 4; ++e) acc[a][b][e] = 0.f;
    run_gemm(smem_u32, tid, mBase, jBase, A2hi, A2lo, Whhi, Whlo, acc);
    float* S = (float*)smem;
    stash_acc(S, acc, tid);
    __syncthreads();

    for (int i = tid; i < MT * JT; i += 256) {
        int jj = i & 31, r = i >> 5;
        int b = mBase + r;
        int j = jBase + jj;
        float ghr = S[r * SST + jj] + bhh[j];
        float ghz = S[r * SST + 32 + jj] + bhh[HID + j];
        float ghn = S[r * SST + 64 + jj] + bhh[2 * HID + j];
        float gir = C1[r * SST + jj] + bih[j];
        float giz = C1[r * SST + 32 + jj] + bih[HID + j];
        float gin = C1[r * SST + 64 + jj] + bih[2 * HID + j];
        float rg = 1.f / (1.f + __expf(-(gir + ghr)));
        float zg = 1.f / (1.f + __expf(-(giz + ghz)));
        float ng = tanhf(gin + rg * ghn);
        float hold = hf[(size_t)b * HID + j];
        float hnew = (1.f - zg) * ng + zg * hold;
        hf[(size_t)b * HID + j] = hnew;
        bf16 hi = __float2bfloat16(hnew);
        out_hi[(size_t)b * HID + j] = hi;
        out_lo[(size_t)b * HID + j] = __float2bfloat16(hnew - __bfloat162float(hi));
    }
}

// y = h2 @ Wout^T + b_out. Wout staged in smem; h rows read as float4.
__global__ void __launch_bounds__(256) y_kernel(
    const float* __restrict__ hf, const float* __restrict__ Wout,
    const float* __restrict__ bout, float* __restrict__ out,
    float* __restrict__ ybuf, int t) {
    __shared__ float ws[NOUT * HID];  // 10240 B
    int tid = threadIdx.x;
    for (int i = tid; i < NOUT * HID; i += 256) ws[i] = Wout[i];
    __syncthreads();
    int wid = tid >> 5, lane = tid & 31;
    int b = blockIdx.x * 8 + wid;
    const float4* hr = (const float4*)(hf + (size_t)b * HID);
    const float4* ws4 = (const float4*)ws;
    float p[NOUT] = {0.f, 0.f, 0.f, 0.f, 0.f};
#pragma unroll
    for (int it = 0; it < 4; ++it) {
        int idx = lane + it * 32;  // float4 index within row (0..127)
        float4 v = hr[idx];
#pragma unroll
        for (int o = 0; o < NOUT; ++o) {
            float4 w = ws4[o * (HID / 4) + idx];
            p[o] += v.x * w.x + v.y * w.y + v.z * w.z + v.w * w.w;
        }
    }
#pragma unroll
    for (int o = 0; o < NOUT; ++o)
#pragma unroll
        for (int off = 16; off; off >>= 1)
            p[o] += __shfl_down_sync(0xffffffffu, p[o], off);
    if (lane == 0) {
#pragma unroll
        for (int o = 0; o < NOUT; ++o) {
            float v = p[o] + bout[o];
            out[(size_t)b * (T_STEPS * NOUT) + t * NOUT + o] = v;
            ybuf[b * NOUT + o] = v;
        }
    }
}

// single fused init: weight hi/lo splits + state splits + y copy (1 launch)
__global__ void init_kernel(
    const float* __restrict__ Whh1, const float* __restrict__ Wih2,
    const float* __restrict__ Whh2, const float* __restrict__ h01,
    const float* __restrict__ h02, const float* __restrict__ y0,
    bf16* __restrict__ whh1hi, bf16* __restrict__ whh1lo,
    bf16* __restrict__ wih2hi, bf16* __restrict__ wih2lo,
    bf16* __restrict__ whh2hi, bf16* __restrict__ whh2lo,
    float* __restrict__ h1f, float* __restrict__ h2f,
    bf16* __restrict__ h1hi, bf16* __restrict__ h1lo,
    bf16* __restrict__ h2hi, bf16* __restrict__ h2lo,
    float* __restrict__ ybuf) {
    int i = blockIdx.x * blockDim.x + threadIdx.x;
    const int NW = G3 * HID;
    const int NS = BATCH * HID;
    if (i < NW) {
        float v = Whh1[i];
        bf16 h = __float2bfloat16(v);
        whh1hi[i] = h;
        whh1lo[i] = __float2bfloat16(v - __bfloat162float(h));
        v = Wih2[i];
        h = __float2bfloat16(v);
        wih2hi[i] = h;
        wih2lo[i] = __float2bfloat16(v - __bfloat162float(h));
        v = Whh2[i];
        h = __float2bfloat16(v);
        whh2hi[i] = h;
        whh2lo[i] = __float2bfloat16(v - __bfloat162float(h));
    }
    if (i < NS) {
        float v = h01[i];
        h1f[i] = v;
        bf16 h = __float2bfloat16(v);
        h1hi[i] = h;
        h1lo[i] = __float2bfloat16(v - __bfloat162float(h));
        v = h02[i];
        h2f[i] = v;
        h = __float2bfloat16(v);
        h2hi[i] = h;
        h2lo[i] = __float2bfloat16(v - __bfloat162float(h));
    }
    if (i < BATCH * NOUT) ybuf[i] = y0[i];
}

extern "C" void kernel_launch(void* const* d_in, const int* in_sizes, int n_in,
                              void* d_out, int out_size) {
    (void)in_sizes; (void)n_in; (void)out_size;
    const float* cmds = (const float*)d_in[1];
    const float* y0 = (const float*)d_in[2];
    const float* h01 = (const float*)d_in[3];
    const float* h02 = (const float*)d_in[4];
    const float* Wih1 = (const float*)d_in[5];
    const float* Whh1 = (const float*)d_in[6];
    const float* bih1 = (const float*)d_in[7];
    const float* bhh1 = (const float*)d_in[8];
    const float* Wih2 = (const float*)d_in[9];
    const float* Whh2 = (const float*)d_in[10];
    const float* bih2 = (const float*)d_in[11];
    const float* bhh2 = (const float*)d_in[12];
    const float* Wout = (const float*)d_in[13];
    const float* bout = (const float*)d_in[14];
    float* out = (float*)d_out;

    void* p;
    float *h1f, *h2f, *ybuf;
    bf16 *h1hi, *h1lo, *h2hi, *h2lo;
    bf16 *whh1hi, *whh1lo, *wih2hi, *wih2lo, *whh2hi, *whh2lo;
    cudaGetSymbolAddress(&p, g_h1f); h1f = (float*)p;
    cudaGetSymbolAddress(&p, g_h2f); h2f = (float*)p;
    cudaGetSymbolAddress(&p, g_y); ybuf = (float*)p;
    cudaGetSymbolAddress(&p, g_h1hi); h1hi = (bf16*)p;
    cudaGetSymbolAddress(&p, g_h1lo); h1lo = (bf16*)p;
    cudaGetSymbolAddress(&p, g_h2hi); h2hi = (bf16*)p;
    cudaGetSymbolAddress(&p, g_h2lo); h2lo = (bf16*)p;
    cudaGetSymbolAddress(&p, g_whh1hi); whh1hi = (bf16*)p;
    cudaGetSymbolAddress(&p, g_whh1lo); whh1lo = (bf16*)p;
    cudaGetSymbolAddress(&p, g_wih2hi); wih2hi = (bf16*)p;
    cudaGetSymbolAddress(&p, g_wih2lo); wih2lo = (bf16*)p;
    cudaGetSymbolAddress(&p, g_whh2hi); whh2hi = (bf16*)p;
    cudaGetSymbolAddress(&p, g_whh2lo); whh2lo = (bf16*)p;

    cudaFuncSetAttribute(l1_kernel, cudaFuncAttributeMaxDynamicSharedMemorySize, L1_SMEM);
    cudaFuncSetAttribute(l2_kernel, cudaFuncAttributeMaxDynamicSharedMemorySize, L2_SMEM);

    const int NS = BATCH * HID;
    init_kernel<<<(NS + 255) / 256, 256>>>(
        Whh1, Wih2, Whh2, h01, h02, y0,
        whh1hi, whh1lo, wih2hi, wih2lo, whh2hi, whh2lo,
        h1f, h2f, h1hi, h1lo, h2hi, h2lo, ybuf);

    dim3 grid(BATCH / MT, HID / JT);
    for (int t = 0; t < T_STEPS; ++t) {
        int cur = t & 1, nxt = (t + 1) & 1;
        bf16* h1hi_c = h1hi + (size_t)cur * NS;
        bf16* h1lo_c = h1lo + (size_t)cur * NS;
        bf16* h1hi_n = h1hi + (size_t)nxt * NS;
        bf16* h1lo_n = h1lo + (size_t)nxt * NS;
        bf16* h2hi_c = h2hi + (size_t)cur * NS;
        bf16* h2lo_c = h2lo + (size_t)cur * NS;
        bf16* h2hi_n = h2hi + (size_t)nxt * NS;
        bf16* h2lo_n = h2lo + (size_t)nxt * NS;
        const float* cmd_t = cmds + (size_t)t * BATCH * NCMD;

        l1_kernel<<<grid, 256, L1_SMEM>>>(
            h1hi_c, h1lo_c, whh1hi, whh1lo, bhh1,
            h1f, h1hi_n, h1lo_n, ybuf, cmd_t, Wih1, bih1);
        l2_kernel<<<grid, 256, L2_SMEM>>>(
            h1hi_n, h1lo_n, wih2hi, wih2lo,
            h2hi_c, h2lo_c, whh2hi, whh2lo,
            bih2, bhh2, h2f, h2hi_n, h2lo_n);
        y_kernel<<<BATCH / 8, 256>>>(h2f, Wout, bout, out, ybuf, t);
    }
}